// round 15
// baseline (speedup 1.0000x reference)
#include <cuda_runtime.h>
#include <cuda_bf16.h>
#include <cuda_fp16.h>
#include <math.h>

// ---------------- problem constants ----------------
#define BB    16
#define NN    1024
#define CC    512
#define LL    77
#define KVLEN 1101
#define NHH   8
#define HDD   64
#define CPG   16
#define EPSV  1e-6f
#define NEGV  -1e10f
#define LOG2E 1.44269504089f

// ---------------- scratch ----------------
__device__ float g_scratch[52224000];
__device__ unsigned g_cnt[128];          // row-block arrival counters (self-resetting)

#define BOFF_XQ   ((size_t)0)
#define BOFF_XKV  ((size_t)8388608)
#define BOFF_T    ((size_t)16777216)
#define BOFF_Q    ((size_t)17408000)
#define BOFF_K    ((size_t)25796608)
#define BOFF_V    ((size_t)34816000)
#define BOFF_ATT  ((size_t)43835392)
#define BOFF_W    ((size_t)52224000)

// ---------------- helpers ----------------
__device__ __forceinline__ unsigned pack_bf16x2(float lo, float hi) {
    unsigned r;
    asm("cvt.rn.bf16x2.f32 %0, %1, %2;" : "=r"(r) : "f"(hi), "f"(lo));
    return r;
}
__device__ __forceinline__ unsigned pack_f16x2(float lo, float hi) {
    unsigned r;
    asm("cvt.rn.f16x2.f32 %0, %1, %2;" : "=r"(r) : "f"(hi), "f"(lo));
    return r;
}
__device__ __forceinline__ unsigned hex2(unsigned x) {
    unsigned r; asm("ex2.approx.f16x2 %0, %1;" : "=r"(r) : "r"(x)); return r;
}
__device__ __forceinline__ unsigned hadd2(unsigned a, unsigned b) {
    unsigned r; asm("add.rn.f16x2 %0, %1, %2;" : "=r"(r) : "r"(a), "r"(b)); return r;
}
__device__ __forceinline__ float2 unpack_h2(unsigned v) {
    __half2 h = *reinterpret_cast<__half2*>(&v);
    return __half22float2(h);
}
__device__ __forceinline__ void mma16(float* c, const unsigned* a, const unsigned* b) {
    asm volatile(
        "mma.sync.aligned.m16n8k16.row.col.f32.bf16.bf16.f32 "
        "{%0,%1,%2,%3},{%4,%5,%6,%7},{%8,%9},{%0,%1,%2,%3};\n"
        : "+f"(c[0]), "+f"(c[1]), "+f"(c[2]), "+f"(c[3])
        : "r"(a[0]), "r"(a[1]), "r"(a[2]), "r"(a[3]), "r"(b[0]), "r"(b[1]));
}
__device__ __forceinline__ void mma16h(float* c, const unsigned* a, const unsigned* b) {
    asm volatile(
        "mma.sync.aligned.m16n8k16.row.col.f32.f16.f16.f32 "
        "{%0,%1,%2,%3},{%4,%5,%6,%7},{%8,%9},{%0,%1,%2,%3};\n"
        : "+f"(c[0]), "+f"(c[1]), "+f"(c[2]), "+f"(c[3])
        : "r"(a[0]), "r"(a[1]), "r"(a[2]), "r"(a[3]), "r"(b[0]), "r"(b[1]));
}
__device__ __forceinline__ void ldsm4(unsigned& r0, unsigned& r1, unsigned& r2, unsigned& r3,
                                      unsigned addr) {
    asm volatile("ldmatrix.sync.aligned.m8n8.x4.shared.b16 {%0,%1,%2,%3}, [%4];"
                 : "=r"(r0), "=r"(r1), "=r"(r2), "=r"(r3) : "r"(addr));
}
__device__ __forceinline__ void ldsm4t(unsigned& r0, unsigned& r1, unsigned& r2, unsigned& r3,
                                       unsigned addr) {
    asm volatile("ldmatrix.sync.aligned.m8n8.x4.trans.shared.b16 {%0,%1,%2,%3}, [%4];"
                 : "=r"(r0), "=r"(r1), "=r"(r2), "=r"(r3) : "r"(addr));
}
__device__ __forceinline__ void cpa16(unsigned dst, const void* src, bool p) {
    int sz = p ? 16 : 0;
    asm volatile("cp.async.cg.shared.global [%0], [%1], 16, %2;\n"
                 :: "r"(dst), "l"(src), "r"(sz));
}
__device__ __forceinline__ void cpa_commit() { asm volatile("cp.async.commit_group;\n"); }
template<int N> __device__ __forceinline__ void cpa_wait() {
    asm volatile("cp.async.wait_group %0;\n" :: "n"(N));
}

struct GemmJob {
    const __nv_bfloat16* A;
    const __nv_bfloat16* W;
    __nv_bfloat16* Out;
    float alpha;
    int out_rows_per_b;
    int out_off;
    int outF16;
};

// =====================================================================
// Fused prologue: gn_img (0..511), gn_txt (512..1023), wconv (1024..1407).
// =====================================================================
__global__ void __launch_bounds__(256, 6)
prep_kernel(const float* __restrict__ x,
            const float* __restrict__ qsc, const float* __restrict__ qbi,
            const float* __restrict__ ksc, const float* __restrict__ kbi,
            const float* __restrict__ te,
            const float* __restrict__ tsc, const float* __restrict__ tbi,
            const float* __restrict__ w0, const float* __restrict__ w1,
            const float* __restrict__ w2, const float* __restrict__ w3,
            const float* __restrict__ w4, const float* __restrict__ w5,
            __nv_bfloat16* __restrict__ oq, __nv_bfloat16* __restrict__ okv,
            __nv_bfloat16* __restrict__ ot, __nv_bfloat16* __restrict__ wout)
{
    int bid = blockIdx.x;
    int tid = threadIdx.x;

    if (bid < 512) {
        int b = bid >> 5, g = bid & 31;
        const float* xb = x + (size_t)b * NN * CC + g * CPG;

        float s = 0.f, s2 = 0.f;
        for (int e = tid; e < NN * 4; e += 256) {
            int n = e >> 2, c4 = (e & 3) << 2;
            float4 v = *(const float4*)(xb + (size_t)n * CC + c4);
            s  += v.x + v.y + v.z + v.w;
            s2 += v.x * v.x + v.y * v.y + v.z * v.z + v.w * v.w;
        }
        #pragma unroll
        for (int o2 = 16; o2; o2 >>= 1) {
            s  += __shfl_xor_sync(0xffffffffu, s,  o2);
            s2 += __shfl_xor_sync(0xffffffffu, s2, o2);
        }
        __shared__ float sh[8], sh2[8];
        int w = tid >> 5, lane = tid & 31;
        if (lane == 0) { sh[w] = s; sh2[w] = s2; }
        __syncthreads();

        __shared__ float cq[2][CPG], ck[2][CPG];
        if (tid < CPG) {
            float ts = 0.f, ts2 = 0.f;
            #pragma unroll
            for (int i = 0; i < 8; i++) { ts += sh[i]; ts2 += sh2[i]; }
            const float cnt = (float)(NN * CPG);
            float mu  = ts / cnt;
            float var = ts2 / cnt - mu * mu;
            float inv = rsqrtf(var + EPSV);
            int c = g * CPG + tid;
            float aq = inv * qsc[c];
            cq[0][tid] = aq;  cq[1][tid] = qbi[c] - mu * aq;
            float ak = inv * ksc[c];
            ck[0][tid] = ak;  ck[1][tid] = kbi[c] - mu * ak;
        }
        __syncthreads();

        __nv_bfloat16* oqb  = oq  + (size_t)b * NN * CC + g * CPG;
        __nv_bfloat16* okvb = okv + (size_t)b * NN * CC + g * CPG;
        for (int e = tid; e < NN * 4; e += 256) {
            int n = e >> 2, c4 = (e & 3) << 2;
            float4 v = *(const float4*)(xb + (size_t)n * CC + c4);
            uint2 pq, pk;
            pq.x = pack_bf16x2(v.x * cq[0][c4+0] + cq[1][c4+0], v.y * cq[0][c4+1] + cq[1][c4+1]);
            pq.y = pack_bf16x2(v.z * cq[0][c4+2] + cq[1][c4+2], v.w * cq[0][c4+3] + cq[1][c4+3]);
            pk.x = pack_bf16x2(v.x * ck[0][c4+0] + ck[1][c4+0], v.y * ck[0][c4+1] + ck[1][c4+1]);
            pk.y = pack_bf16x2(v.z * ck[0][c4+2] + ck[1][c4+2], v.w * ck[0][c4+3] + ck[1][c4+3]);
            *(uint2*)(oqb  + (size_t)n * CC + c4) = pq;
            *(uint2*)(okvb + (size_t)n * CC + c4) = pk;
        }
    } else if (bid < 1024) {
        int b = (bid - 512) >> 5, g = (bid - 512) & 31;
        const float* xb = te + (size_t)b * LL * CC + g * CPG;

        float s = 0.f, s2 = 0.f;
        for (int e = tid; e < LL * 4; e += 256) {
            int n = e >> 2, c4 = (e & 3) << 2;
            float4 v = *(const float4*)(xb + (size_t)n * CC + c4);
            s  += v.x + v.y + v.z + v.w;
            s2 += v.x * v.x + v.y * v.y + v.z * v.z + v.w * v.w;
        }
        #pragma unroll
        for (int o2 = 16; o2; o2 >>= 1) {
            s  += __shfl_xor_sync(0xffffffffu, s,  o2);
            s2 += __shfl_xor_sync(0xffffffffu, s2, o2);
        }
        __shared__ float th[8], th2[8];
        int w = tid >> 5, lane = tid & 31;
        if (lane == 0) { th[w] = s; th2[w] = s2; }
        __syncthreads();

        __shared__ float ct[2][CPG];
        if (tid < CPG) {
            float ts = 0.f, ts2 = 0.f;
            #pragma unroll
            for (int i = 0; i < 8; i++) { ts += th[i]; ts2 += th2[i]; }
            const float cnt = (float)(LL * CPG);
            float mu  = ts / cnt;
            float var = ts2 / cnt - mu * mu;
            float inv = rsqrtf(var + EPSV);
            int c = g * CPG + tid;
            float a = inv * tsc[c];
            ct[0][tid] = a;  ct[1][tid] = tbi[c] - mu * a;
        }
        __syncthreads();

        __nv_bfloat16* ob = ot + (size_t)b * LL * CC + g * CPG;
        for (int e = tid; e < LL * 4; e += 256) {
            int n = e >> 2, c4 = (e & 3) << 2;
            float4 v = *(const float4*)(xb + (size_t)n * CC + c4);
            uint2 p;
            p.x = pack_bf16x2(v.x * ct[0][c4+0] + ct[1][c4+0], v.y * ct[0][c4+1] + ct[1][c4+1]);
            p.y = pack_bf16x2(v.z * ct[0][c4+2] + ct[1][c4+2], v.w * ct[0][c4+3] + ct[1][c4+3]);
            *(uint2*)(ob + (size_t)n * CC + c4) = p;
        }
    } else {
        int gid = (bid - 1024) * 256 + tid;
        #pragma unroll
        for (int i = 0; i < 4; i++) {
            int f4 = gid * 4 + i;
            int mat = f4 >> 16;
            int idx = (f4 & 65535) << 2;
            const float* src = mat == 0 ? w0 : mat == 1 ? w1 : mat == 2 ? w2
                             : mat == 3 ? w3 : mat == 4 ? w4 : w5;
            float4 v = *(const float4*)(src + idx);
            uint2 p;
            p.x = pack_bf16x2(v.x, v.y);
            p.y = pack_bf16x2(v.z, v.w);
            *(uint2*)(wout + (size_t)mat * 262144 + idx) = p;
        }
    }
}

// =====================================================================
// BF16 GEMM core (3-stage cp.async pipeline, BK=64, block 128x128).
// =====================================================================
__device__ __forceinline__ void gemm_core(
    const __nv_bfloat16* __restrict__ A, const __nv_bfloat16* __restrict__ W,
    int M, int m0, int n0, unsigned aBase, unsigned bBase, float acc[4][4][4],
    int tid, int lane, int wm, int wn)
{
    auto loadTile = [&](int kt, int st) {
        int k0 = kt * 64;
        unsigned aD = aBase + st * 16384;
        unsigned bD = bBase + st * 16384;
        #pragma unroll
        for (int i = 0; i < 4; i++) {
            int f = tid + i * 256;
            int r = f >> 3, c = f & 7;
            bool ok = (m0 + r) < M;
            cpa16(aD + r * 128 + ((c ^ (r & 7)) << 4),
                  A + (size_t)(m0 + r) * 512 + k0 + c * 8, ok);
        }
        #pragma unroll
        for (int i = 0; i < 4; i++) {
            int f = tid + i * 256;
            int r = f >> 4, c = f & 15;
            cpa16(bD + r * 256 + ((c ^ (r & 7)) << 4),
                  W + (size_t)(k0 + r) * 512 + n0 + c * 8, true);
        }
    };
    loadTile(0, 0); cpa_commit();
    loadTile(1, 1); cpa_commit();

    int st = 0;
    for (int t = 0; t < 8; t++) {
        cpa_wait<1>();
        __syncthreads();
        if (t + 2 < 8) {
            int ns = st + 2; if (ns >= 3) ns -= 3;
            loadTile(t + 2, ns);
            cpa_commit();
        }
        unsigned aC = aBase + st * 16384;
        unsigned bC = bBase + st * 16384;
        #pragma unroll
        for (int kc = 0; kc < 8; kc += 2) {
            unsigned af[4][4];
            #pragma unroll
            for (int i = 0; i < 4; i++) {
                int r = wm + i * 16 + (lane & 15);
                int c = kc + (lane >> 4);
                ldsm4(af[i][0], af[i][1], af[i][2], af[i][3],
                      aC + r * 128 + ((c ^ (r & 7)) << 4));
            }
            unsigned bfr[4][2];
            #pragma unroll
            for (int grp = 0; grp < 2; grp++) {
                int r = kc * 8 + (lane & 15);
                int c = (wn >> 3) + 2 * grp + (lane >> 4);
                unsigned r0, r1, r2, r3;
                ldsm4t(r0, r1, r2, r3, bC + r * 256 + ((c ^ (r & 7)) << 4));
                bfr[grp*2][0] = r0;   bfr[grp*2][1] = r1;
                bfr[grp*2+1][0] = r2; bfr[grp*2+1][1] = r3;
            }
            #pragma unroll
            for (int i = 0; i < 4; i++)
                #pragma unroll
                for (int j = 0; j < 4; j++)
                    mma16(acc[i][j], af[i], bfr[j]);
        }
        if (++st == 3) st = 0;
    }
}

#define GEMM_SMEM 98304

// Persistent: each block strides over all 1616 projection tiles.
__global__ void __launch_bounds__(256, 2)
gemm_all(GemmJob j0, GemmJob j1, GemmJob j2, GemmJob j3, GemmJob j4)
{
    extern __shared__ char smc[];
    unsigned aBase = (unsigned)__cvta_generic_to_shared(smc);
    unsigned bBase = aBase + 3 * 16384;

    int tid = threadIdx.x, warp = tid >> 5, lane = tid & 31;
    int g = lane >> 2, tg = lane & 3;
    int wm = (warp >> 2) * 64, wn = (warp & 3) * 32;

    for (int bx = blockIdx.x; bx < 1616; bx += gridDim.x) {
        GemmJob jb;
        int M, rows_per_b, m0, n0;
        if (bx < 1536) {
            int z = bx >> 9;
            int r = bx & 511;
            jb = z == 0 ? j0 : z == 1 ? j1 : j2;
            m0 = (r >> 2) * 128; n0 = (r & 3) * 128;
            M = 16384; rows_per_b = 1024;
        } else {
            int c = bx - 1536;
            jb = (c < 40) ? j3 : j4;
            int r = c % 40;
            m0 = (r >> 2) * 128; n0 = (r & 3) * 128;
            M = 1232; rows_per_b = 77;
        }

        __syncthreads();
        float acc[4][4][4] = {};
        gemm_core(jb.A, jb.W, M, m0, n0, aBase, bBase, acc, tid, lane, wm, wn);

        #pragma unroll
        for (int i = 0; i < 4; i++) {
            #pragma unroll
            for (int rs = 0; rs < 2; rs++) {
                int gm = m0 + wm + i * 16 + g + rs * 8;
                if (gm >= M) continue;
                int bbi = gm / rows_per_b;
                int rr  = gm - bbi * rows_per_b;
                size_t orow = (size_t)bbi * jb.out_rows_per_b + jb.out_off + rr;
                #pragma unroll
                for (int j = 0; j < 4; j++) {
                    int col = n0 + wn + j * 8 + 2 * tg;
                    float v0 = acc[i][j][rs * 2 + 0] * jb.alpha;
                    float v1 = acc[i][j][rs * 2 + 1] * jb.alpha;
                    *(unsigned*)(jb.Out + orow * 512 + col) =
                        jb.outF16 ? pack_f16x2(v0, v1) : pack_bf16x2(v0, v1);
                }
            }
        }
    }
}

// =====================================================================
// Persistent attention + dataflow-fused final projection.
// Attention: 8 warps x 16 q-rows, no-max softmax (f16x2 exp2), P/V f16.
// After each item, bump the (b,qt) row-block counter; the 8th arrival
// immediately computes that row-block's 4 final-GEMM tiles (fp32 + res).
// =====================================================================
#define ATT_SMEM (98304 + 768)

__global__ void __launch_bounds__(256, 2)
attn_fused(const int* __restrict__ tmask,
           const __nv_bfloat16* __restrict__ Qg,
           const __nv_bfloat16* __restrict__ Kg,
           const __nv_bfloat16* __restrict__ Vg,   // f16 bits
           __nv_bfloat16* __restrict__ ATTb,
           const __nv_bfloat16* __restrict__ Wo,
           float* __restrict__ Out, const float* __restrict__ Res)
{
    extern __shared__ char smc[];
    unsigned qB  = (unsigned)__cvta_generic_to_shared(smc);
    unsigned kvB = qB + 16384;
    float* kmaskf = (float*)(smc + 98304);
    __shared__ int trig;

    int tid = threadIdx.x, warp = tid >> 5, lane = tid & 31;
    int g = lane >> 2, tg = lane & 3;
    int wm = warp * 16;

    for (int wk = blockIdx.x; wk < 1024; wk += gridDim.x) {
        int qt = wk & 7, h = (wk >> 3) & 7, b = wk >> 6;

        const __nv_bfloat16* qb = Qg + (size_t)(b * NN + qt * 128) * 512 + h * 64;
        const __nv_bfloat16* kb = Kg + (size_t)b * KVLEN * 512 + h * 64;
        const __nv_bfloat16* vb = Vg + (size_t)b * KVLEN * 512 + h * 64;
        const int* tm = tmask + b * LL;

        __syncthreads();

        #pragma unroll
        for (int i = 0; i < 4; i++) {
            int f = tid + i * 256;
            int r = f >> 3, c = f & 7;
            cpa16(qB + r * 128 + ((c ^ (r & 7)) << 4), qb + (size_t)r * 512 + c * 8, true);
        }

        auto loadKV = [&](int t, int stg) {
            int kv0 = t * 64;
            unsigned kD = kvB + stg * 16384, vD = kD + 8192;
            #pragma unroll
            for (int i = 0; i < 2; i++) {
                int f = tid + i * 256;
                int r = f >> 3, c = f & 7;
                int kg = kv0 + r;
                bool ok = kg < KVLEN;
                cpa16(kD + r * 128 + ((c ^ (r & 7)) << 4), kb + (size_t)kg * 512 + c * 8, ok);
                cpa16(vD + r * 128 + ((c ^ (r & 7)) << 4), vb + (size_t)kg * 512 + c * 8, ok);
            }
            if (kv0 + 64 > NN && tid < 64) {
                int kg = kv0 + tid;
                float m = 0.f;
                if (kg >= KVLEN) m = NEGV * LOG2E;
                else if (kg >= NN && tm[kg - NN] == 0) m = NEGV * LOG2E;
                kmaskf[stg * 64 + tid] = m;
            }
        };
        loadKV(0, 0); cpa_commit();
        loadKV(1, 1); cpa_commit();

        float l_i[2] = {0.f, 0.f}, o[8][4] = {};

        int st = 0;
        for (int t = 0; t < 18; t++) {
            if (t < 17) cpa_wait<1>(); else cpa_wait<0>();
            __syncthreads();
            if (t + 2 < 18) {
                int ns = st + 2; if (ns >= 3) ns -= 3;
                loadKV(t + 2, ns);
                cpa_commit();
            }

            unsigned kC = kvB + st * 16384;
            unsigned vC = kC + 8192;
            const float* km = kmaskf + st * 64;
            bool masked = (t * 64 + 64 > NN);

            // ---- S = Q K^T (bf16) ----
            float s[8][4] = {};
            #pragma unroll
            for (int kc = 0; kc < 8; kc += 2) {
                unsigned aq[4];
                {
                    int r = wm + (lane & 15);
                    int c = kc + (lane >> 4);
                    ldsm4(aq[0], aq[1], aq[2], aq[3], qB + r * 128 + ((c ^ (r & 7)) << 4));
                }
                #pragma unroll
                for (int grp = 0; grp < 4; grp++) {
                    int r = grp * 16 + (lane & 7) + ((lane >> 4) << 3);
                    int c = kc + ((lane >> 3) & 1);
                    unsigned r0, r1, r2, r3;
                    ldsm4(r0, r1, r2, r3, kC + r * 128 + ((c ^ (r & 7)) << 4));
                    unsigned bk0[2] = {r0, r1}, bk1[2] = {r2, r3};
                    mma16(s[grp * 2], aq, bk0);
                    mma16(s[grp * 2 + 1], aq, bk1);
                }
            }

            if (masked) {
                #pragma unroll
                for (int j = 0; j < 8; j++) {
                    float k0v = km[j * 8 + 2 * tg], k1v = km[j * 8 + 2 * tg + 1];
                    s[j][0] += k0v; s[j][1] += k1v;
                    s[j][2] += k0v; s[j][3] += k1v;
                }
            }

            // ---- no-max softmax via f16x2 exp2, interleaved with P·V ----
            unsigned acc0 = 0u, acc1 = 0u;
            #pragma unroll
            for (int kc2 = 0; kc2 < 4; kc2++) {
                unsigned pp[4];
                pp[0] = hex2(pack_f16x2(s[2*kc2][0],   s[2*kc2][1]));
                pp[1] = hex2(pack_f16x2(s[2*kc2][2],   s[2*kc2][3]));
                pp[2] = hex2(pack_f16x2(s[2*kc2+1][0], s[2*kc2+1][1]));
                pp[3] = hex2(pack_f16x2(s[2*kc2+1][2], s[2*kc2+1][3]));
                acc0 = hadd2(acc0, hadd2(pp[0], pp[2]));
                acc1 = hadd2(acc1, hadd2(pp[1], pp[3]));
                #pragma unroll
                for (int grp = 0; grp < 4; grp++) {
                    int r = kc2 * 16 + (lane & 15);
                    int c = grp * 2 + (lane >> 4);
                    unsigned r0, r1, r2, r3;
                    ldsm4t(r0, r1, r2, r3, vC + r * 128 + ((c ^ (r & 7)) << 4));
                    unsigned bv0[2] = {r0, r1}, bv1[2] = {r2, r3};
                    mma16h(o[grp * 2], pp, bv0);
                    mma16h(o[grp * 2 + 1], pp, bv1);
                }
            }
            float2 s0 = unpack_h2(acc0);
            float2 s1 = unpack_h2(acc1);
            l_i[0] += s0.x + s0.y;
            l_i[1] += s1.x + s1.y;

            if (++st == 3) st = 0;
        }

        l_i[0] += __shfl_xor_sync(0xffffffffu, l_i[0], 1);
        l_i[0] += __shfl_xor_sync(0xffffffffu, l_i[0], 2);
        l_i[1] += __shfl_xor_sync(0xffffffffu, l_i[1], 1);
        l_i[1] += __shfl_xor_sync(0xffffffffu, l_i[1], 2);

        __nv_bfloat16* ob = ATTb + (size_t)(b * NN + qt * 128) * 512 + h * 64;
        #pragma unroll
        for (int rs = 0; rs < 2; rs++) {
            int r = wm + g + rs * 8;
            float inv = 1.f / l_i[rs];
            #pragma unroll
            for (int j = 0; j < 8; j++) {
                int col = j * 8 + 2 * tg;
                *(unsigned*)(ob + (size_t)r * 512 + col) =
                    pack_bf16x2(o[j][rs * 2 + 0] * inv, o[j][rs * 2 + 1] * inv);
            }
        }

        // ---- publish + dataflow trigger of final projection ----
        __threadfence();
        __syncthreads();
        if (tid == 0) {
            int rb = b * 8 + qt;
            unsigned old = atomicAdd(&g_cnt[rb], 1u);
            if (old == 7u) { g_cnt[rb] = 0u; trig = rb; }
            else trig = -1;
        }
        __syncthreads();
        int rb = trig;
        if (rb >= 0) {
            __threadfence();   // acquire: other blocks' ATTb writes now visible
            unsigned aBase = qB;                  // reuse full 96KB smem
            unsigned bBase = qB + 3 * 16384;
            int gw = warp, gl = lane;
            int gg = gl >> 2, gtg = gl & 3;
            int gwm = (gw >> 2) * 64, gwn = (gw & 3) * 32;
            int m0 = rb * 128;
            for (int nt = 0; nt < 4; nt++) {
                __syncthreads();
                float acc[4][4][4] = {};
                gemm_core(ATTb, Wo, 16384, m0, nt * 128, aBase, bBase, acc,
                          tid, gl, gwm, gwn);
                #pragma unroll
                for (int i = 0; i < 4; i++) {
                    #pragma unroll
                    for (int rs = 0; rs < 2; rs++) {
                        size_t orow = (size_t)(m0 + gwm + i * 16 + gg + rs * 8);
                        #pragma unroll
                        for (int j = 0; j < 4; j++) {
                            int col = nt * 128 + gwn + j * 8 + 2 * gtg;
                            float2 rv = *(const float2*)(Res + orow * 512 + col);
                            *(float2*)(Out + orow * 512 + col) =
                                make_float2(acc[i][j][rs * 2 + 0] + rv.x,
                                            acc[i][j][rs * 2 + 1] + rv.y);
                        }
                    }
                }
            }
        }
    }
}

// =====================================================================
// launch
// =====================================================================
extern "C" void kernel_launch(void* const* d_in, const int* in_sizes, int n_in,
                              void* d_out, int out_size)
{
    const float* x    = (const float*)d_in[0];
    const float* te   = (const float*)d_in[1];
    const int*   tmk  = (const int*)  d_in[2];
    const float* gqs  = (const float*)d_in[3];
    const float* gqb  = (const float*)d_in[4];
    const float* gks  = (const float*)d_in[5];
    const float* gkb  = (const float*)d_in[6];
    const float* gts  = (const float*)d_in[7];
    const float* gtb  = (const float*)d_in[8];
    const float* Wq   = (const float*)d_in[9];
    const float* Wks  = (const float*)d_in[10];
    const float* Wvs  = (const float*)d_in[11];
    const float* Wkc  = (const float*)d_in[12];
    const float* Wvc  = (const float*)d_in[13];
    const float* Wout = (const float*)d_in[14];
    float* out = (float*)d_out;

    float* scratch = nullptr;
    cudaGetSymbolAddress((void**)&scratch, g_scratch);
    __nv_bfloat16* bs = (__nv_bfloat16*)scratch;
    __nv_bfloat16* XQ   = bs + BOFF_XQ;
    __nv_bfloat16* XKV  = bs + BOFF_XKV;
    __nv_bfloat16* Tb   = bs + BOFF_T;
    __nv_bfloat16* Qb   = bs + BOFF_Q;
    __nv_bfloat16* Kb   = bs + BOFF_K;
    __nv_bfloat16* Vb   = bs + BOFF_V;
    __nv_bfloat16* ATTb = bs + BOFF_ATT;
    __nv_bfloat16* Wb   = bs + BOFF_W;

    int nsm = 148;
    cudaDeviceGetAttribute(&nsm, cudaDevAttrMultiProcessorCount, 0);
    int pgrid = 2 * nsm;

    cudaFuncSetAttribute(gemm_all, cudaFuncAttributeMaxDynamicSharedMemorySize, GEMM_SMEM);
    cudaFuncSetAttribute(attn_fused, cudaFuncAttributeMaxDynamicSharedMemorySize, ATT_SMEM);

    prep_kernel<<<1408, 256>>>(x, gqs, gqb, gks, gkb,
                               te, gts, gtb,
                               Wq, Wks, Wvs, Wkc, Wvc, Wout,
                               XQ, XKV, Tb, Wb);

    __nv_bfloat16* WqB  = Wb;
    __nv_bfloat16* WksB = Wb + 262144;
    __nv_bfloat16* WvsB = Wb + 2 * 262144;
    __nv_bfloat16* WkcB = Wb + 3 * 262144;
    __nv_bfloat16* WvcB = Wb + 4 * 262144;
    __nv_bfloat16* WoB  = Wb + 5 * 262144;

    GemmJob jq  = { XQ,  WqB,  Qb, 0.125f * LOG2E, 1024,  0,    0 };
    GemmJob jk  = { XKV, WksB, Kb, 1.f,            KVLEN, 0,    0 };
    GemmJob jv  = { XKV, WvsB, Vb, 1.f,            KVLEN, 0,    1 };
    GemmJob jkc = { Tb,  WkcB, Kb, 1.f,            KVLEN, 1024, 0 };
    GemmJob jvc = { Tb,  WvcB, Vb, 1.f,            KVLEN, 1024, 1 };
    gemm_all<<<pgrid, 256, GEMM_SMEM>>>(jq, jk, jv, jkc, jvc);

    attn_fused<<<pgrid, 256, ATT_SMEM>>>(tmk, Qb, Kb, Vb, ATTb, WoB, out, x);
}

// round 16
// speedup vs baseline: 2.0018x; 2.0018x over previous
#include <cuda_runtime.h>
#include <cuda_bf16.h>
#include <cuda_fp16.h>
#include <math.h>

// ---------------- problem constants ----------------
#define BB    16
#define NN    1024
#define CC    512
#define LL    77
#define KVLEN 1101
#define NHH   8
#define HDD   64
#define CPG   16
#define EPSV  1e-6f
#define NEGV  -1e10f
#define LOG2E 1.44269504089f

// ---------------- scratch ----------------
__device__ float g_scratch[52224000];

#define BOFF_XQ   ((size_t)0)
#define BOFF_XKV  ((size_t)8388608)
#define BOFF_T    ((size_t)16777216)
#define BOFF_Q    ((size_t)17408000)
#define BOFF_K    ((size_t)25796608)
#define BOFF_V    ((size_t)34816000)
#define BOFF_ATT  ((size_t)43835392)
#define BOFF_W    ((size_t)52224000)

// ---------------- helpers ----------------
__device__ __forceinline__ unsigned pack_bf16x2(float lo, float hi) {
    unsigned r;
    asm("cvt.rn.bf16x2.f32 %0, %1, %2;" : "=r"(r) : "f"(hi), "f"(lo));
    return r;
}
__device__ __forceinline__ unsigned pack_f16x2(float lo, float hi) {
    unsigned r;
    asm("cvt.rn.f16x2.f32 %0, %1, %2;" : "=r"(r) : "f"(hi), "f"(lo));
    return r;
}
__device__ __forceinline__ unsigned hex2(unsigned x) {
    unsigned r; asm("ex2.approx.f16x2 %0, %1;" : "=r"(r) : "r"(x)); return r;
}
__device__ __forceinline__ unsigned hadd2(unsigned a, unsigned b) {
    unsigned r; asm("add.rn.f16x2 %0, %1, %2;" : "=r"(r) : "r"(a), "r"(b)); return r;
}
__device__ __forceinline__ float2 unpack_h2(unsigned v) {
    __half2 h = *reinterpret_cast<__half2*>(&v);
    return __half22float2(h);
}
__device__ __forceinline__ void mma16(float* c, const unsigned* a, const unsigned* b) {
    asm volatile(
        "mma.sync.aligned.m16n8k16.row.col.f32.bf16.bf16.f32 "
        "{%0,%1,%2,%3},{%4,%5,%6,%7},{%8,%9},{%0,%1,%2,%3};\n"
        : "+f"(c[0]), "+f"(c[1]), "+f"(c[2]), "+f"(c[3])
        : "r"(a[0]), "r"(a[1]), "r"(a[2]), "r"(a[3]), "r"(b[0]), "r"(b[1]));
}
__device__ __forceinline__ void mma16h(float* c, const unsigned* a, const unsigned* b) {
    asm volatile(
        "mma.sync.aligned.m16n8k16.row.col.f32.f16.f16.f32 "
        "{%0,%1,%2,%3},{%4,%5,%6,%7},{%8,%9},{%0,%1,%2,%3};\n"
        : "+f"(c[0]), "+f"(c[1]), "+f"(c[2]), "+f"(c[3])
        : "r"(a[0]), "r"(a[1]), "r"(a[2]), "r"(a[3]), "r"(b[0]), "r"(b[1]));
}
__device__ __forceinline__ void ldsm4(unsigned& r0, unsigned& r1, unsigned& r2, unsigned& r3,
                                      unsigned addr) {
    asm volatile("ldmatrix.sync.aligned.m8n8.x4.shared.b16 {%0,%1,%2,%3}, [%4];"
                 : "=r"(r0), "=r"(r1), "=r"(r2), "=r"(r3) : "r"(addr));
}
__device__ __forceinline__ void ldsm4t(unsigned& r0, unsigned& r1, unsigned& r2, unsigned& r3,
                                       unsigned addr) {
    asm volatile("ldmatrix.sync.aligned.m8n8.x4.trans.shared.b16 {%0,%1,%2,%3}, [%4];"
                 : "=r"(r0), "=r"(r1), "=r"(r2), "=r"(r3) : "r"(addr));
}
__device__ __forceinline__ void cpa16(unsigned dst, const void* src, bool p) {
    int sz = p ? 16 : 0;
    asm volatile("cp.async.cg.shared.global [%0], [%1], 16, %2;\n"
                 :: "r"(dst), "l"(src), "r"(sz));
}
__device__ __forceinline__ void cpa_commit() { asm volatile("cp.async.commit_group;\n"); }
template<int N> __device__ __forceinline__ void cpa_wait() {
    asm volatile("cp.async.wait_group %0;\n" :: "n"(N));
}

struct GemmJob {
    const __nv_bfloat16* A;
    const __nv_bfloat16* W;
    __nv_bfloat16* Out;
    float alpha;
    int out_rows_per_b;
    int out_off;
    int outF16;
};

// =====================================================================
// Fused prologue: gn_img (0..511), gn_txt (512..1023), wconv (1024..1407).
// =====================================================================
__global__ void __launch_bounds__(256, 6)
prep_kernel(const float* __restrict__ x,
            const float* __restrict__ qsc, const float* __restrict__ qbi,
            const float* __restrict__ ksc, const float* __restrict__ kbi,
            const float* __restrict__ te,
            const float* __restrict__ tsc, const float* __restrict__ tbi,
            const float* __restrict__ w0, const float* __restrict__ w1,
            const float* __restrict__ w2, const float* __restrict__ w3,
            const float* __restrict__ w4, const float* __restrict__ w5,
            __nv_bfloat16* __restrict__ oq, __nv_bfloat16* __restrict__ okv,
            __nv_bfloat16* __restrict__ ot, __nv_bfloat16* __restrict__ wout)
{
    int bid = blockIdx.x;
    int tid = threadIdx.x;

    if (bid < 512) {
        int b = bid >> 5, g = bid & 31;
        const float* xb = x + (size_t)b * NN * CC + g * CPG;

        float s = 0.f, s2 = 0.f;
        for (int e = tid; e < NN * 4; e += 256) {
            int n = e >> 2, c4 = (e & 3) << 2;
            float4 v = *(const float4*)(xb + (size_t)n * CC + c4);
            s  += v.x + v.y + v.z + v.w;
            s2 += v.x * v.x + v.y * v.y + v.z * v.z + v.w * v.w;
        }
        #pragma unroll
        for (int o2 = 16; o2; o2 >>= 1) {
            s  += __shfl_xor_sync(0xffffffffu, s,  o2);
            s2 += __shfl_xor_sync(0xffffffffu, s2, o2);
        }
        __shared__ float sh[8], sh2[8];
        int w = tid >> 5, lane = tid & 31;
        if (lane == 0) { sh[w] = s; sh2[w] = s2; }
        __syncthreads();

        __shared__ float cq[2][CPG], ck[2][CPG];
        if (tid < CPG) {
            float ts = 0.f, ts2 = 0.f;
            #pragma unroll
            for (int i = 0; i < 8; i++) { ts += sh[i]; ts2 += sh2[i]; }
            const float cnt = (float)(NN * CPG);
            float mu  = ts / cnt;
            float var = ts2 / cnt - mu * mu;
            float inv = rsqrtf(var + EPSV);
            int c = g * CPG + tid;
            float aq = inv * qsc[c];
            cq[0][tid] = aq;  cq[1][tid] = qbi[c] - mu * aq;
            float ak = inv * ksc[c];
            ck[0][tid] = ak;  ck[1][tid] = kbi[c] - mu * ak;
        }
        __syncthreads();

        __nv_bfloat16* oqb  = oq  + (size_t)b * NN * CC + g * CPG;
        __nv_bfloat16* okvb = okv + (size_t)b * NN * CC + g * CPG;
        for (int e = tid; e < NN * 4; e += 256) {
            int n = e >> 2, c4 = (e & 3) << 2;
            float4 v = *(const float4*)(xb + (size_t)n * CC + c4);
            uint2 pq, pk;
            pq.x = pack_bf16x2(v.x * cq[0][c4+0] + cq[1][c4+0], v.y * cq[0][c4+1] + cq[1][c4+1]);
            pq.y = pack_bf16x2(v.z * cq[0][c4+2] + cq[1][c4+2], v.w * cq[0][c4+3] + cq[1][c4+3]);
            pk.x = pack_bf16x2(v.x * ck[0][c4+0] + ck[1][c4+0], v.y * ck[0][c4+1] + ck[1][c4+1]);
            pk.y = pack_bf16x2(v.z * ck[0][c4+2] + ck[1][c4+2], v.w * ck[0][c4+3] + ck[1][c4+3]);
            *(uint2*)(oqb  + (size_t)n * CC + c4) = pq;
            *(uint2*)(okvb + (size_t)n * CC + c4) = pk;
        }
    } else if (bid < 1024) {
        int b = (bid - 512) >> 5, g = (bid - 512) & 31;
        const float* xb = te + (size_t)b * LL * CC + g * CPG;

        float s = 0.f, s2 = 0.f;
        for (int e = tid; e < LL * 4; e += 256) {
            int n = e >> 2, c4 = (e & 3) << 2;
            float4 v = *(const float4*)(xb + (size_t)n * CC + c4);
            s  += v.x + v.y + v.z + v.w;
            s2 += v.x * v.x + v.y * v.y + v.z * v.z + v.w * v.w;
        }
        #pragma unroll
        for (int o2 = 16; o2; o2 >>= 1) {
            s  += __shfl_xor_sync(0xffffffffu, s,  o2);
            s2 += __shfl_xor_sync(0xffffffffu, s2, o2);
        }
        __shared__ float th[8], th2[8];
        int w = tid >> 5, lane = tid & 31;
        if (lane == 0) { th[w] = s; th2[w] = s2; }
        __syncthreads();

        __shared__ float ct[2][CPG];
        if (tid < CPG) {
            float ts = 0.f, ts2 = 0.f;
            #pragma unroll
            for (int i = 0; i < 8; i++) { ts += th[i]; ts2 += th2[i]; }
            const float cnt = (float)(LL * CPG);
            float mu  = ts / cnt;
            float var = ts2 / cnt - mu * mu;
            float inv = rsqrtf(var + EPSV);
            int c = g * CPG + tid;
            float a = inv * tsc[c];
            ct[0][tid] = a;  ct[1][tid] = tbi[c] - mu * a;
        }
        __syncthreads();

        __nv_bfloat16* ob = ot + (size_t)b * LL * CC + g * CPG;
        for (int e = tid; e < LL * 4; e += 256) {
            int n = e >> 2, c4 = (e & 3) << 2;
            float4 v = *(const float4*)(xb + (size_t)n * CC + c4);
            uint2 p;
            p.x = pack_bf16x2(v.x * ct[0][c4+0] + ct[1][c4+0], v.y * ct[0][c4+1] + ct[1][c4+1]);
            p.y = pack_bf16x2(v.z * ct[0][c4+2] + ct[1][c4+2], v.w * ct[0][c4+3] + ct[1][c4+3]);
            *(uint2*)(ob + (size_t)n * CC + c4) = p;
        }
    } else {
        int gid = (bid - 1024) * 256 + tid;
        #pragma unroll
        for (int i = 0; i < 4; i++) {
            int f4 = gid * 4 + i;
            int mat = f4 >> 16;
            int idx = (f4 & 65535) << 2;
            const float* src = mat == 0 ? w0 : mat == 1 ? w1 : mat == 2 ? w2
                             : mat == 3 ? w3 : mat == 4 ? w4 : w5;
            float4 v = *(const float4*)(src + idx);
            uint2 p;
            p.x = pack_bf16x2(v.x, v.y);
            p.y = pack_bf16x2(v.z, v.w);
            *(uint2*)(wout + (size_t)mat * 262144 + idx) = p;
        }
    }
}

// =====================================================================
// BF16 GEMM core (3-stage cp.async pipeline, BK=64, block 128x128).
// =====================================================================
__device__ __forceinline__ void gemm_core(
    const __nv_bfloat16* __restrict__ A, const __nv_bfloat16* __restrict__ W,
    int M, int m0, int n0, unsigned aBase, unsigned bBase, float acc[4][4][4],
    int tid, int lane, int wm, int wn)
{
    auto loadTile = [&](int kt, int st) {
        int k0 = kt * 64;
        unsigned aD = aBase + st * 16384;
        unsigned bD = bBase + st * 16384;
        #pragma unroll
        for (int i = 0; i < 4; i++) {
            int f = tid + i * 256;
            int r = f >> 3, c = f & 7;
            bool ok = (m0 + r) < M;
            cpa16(aD + r * 128 + ((c ^ (r & 7)) << 4),
                  A + (size_t)(m0 + r) * 512 + k0 + c * 8, ok);
        }
        #pragma unroll
        for (int i = 0; i < 4; i++) {
            int f = tid + i * 256;
            int r = f >> 4, c = f & 15;
            cpa16(bD + r * 256 + ((c ^ (r & 7)) << 4),
                  W + (size_t)(k0 + r) * 512 + n0 + c * 8, true);
        }
    };
    loadTile(0, 0); cpa_commit();
    loadTile(1, 1); cpa_commit();

    int st = 0;
    for (int t = 0; t < 8; t++) {
        cpa_wait<1>();
        __syncthreads();
        if (t + 2 < 8) {
            int ns = st + 2; if (ns >= 3) ns -= 3;
            loadTile(t + 2, ns);
            cpa_commit();
        }
        unsigned aC = aBase + st * 16384;
        unsigned bC = bBase + st * 16384;
        #pragma unroll
        for (int kc = 0; kc < 8; kc += 2) {
            unsigned af[4][4];
            #pragma unroll
            for (int i = 0; i < 4; i++) {
                int r = wm + i * 16 + (lane & 15);
                int c = kc + (lane >> 4);
                ldsm4(af[i][0], af[i][1], af[i][2], af[i][3],
                      aC + r * 128 + ((c ^ (r & 7)) << 4));
            }
            unsigned bfr[4][2];
            #pragma unroll
            for (int grp = 0; grp < 2; grp++) {
                int r = kc * 8 + (lane & 15);
                int c = (wn >> 3) + 2 * grp + (lane >> 4);
                unsigned r0, r1, r2, r3;
                ldsm4t(r0, r1, r2, r3, bC + r * 256 + ((c ^ (r & 7)) << 4));
                bfr[grp*2][0] = r0;   bfr[grp*2][1] = r1;
                bfr[grp*2+1][0] = r2; bfr[grp*2+1][1] = r3;
            }
            #pragma unroll
            for (int i = 0; i < 4; i++)
                #pragma unroll
                for (int j = 0; j < 4; j++)
                    mma16(acc[i][j], af[i], bfr[j]);
        }
        if (++st == 3) st = 0;
    }
}

#define GEMM_SMEM 98304

// Persistent: each block strides over all 1616 projection tiles.
__global__ void __launch_bounds__(256, 2)
gemm_all(GemmJob j0, GemmJob j1, GemmJob j2, GemmJob j3, GemmJob j4)
{
    extern __shared__ char smc[];
    unsigned aBase = (unsigned)__cvta_generic_to_shared(smc);
    unsigned bBase = aBase + 3 * 16384;

    int tid = threadIdx.x, warp = tid >> 5, lane = tid & 31;
    int g = lane >> 2, tg = lane & 3;
    int wm = (warp >> 2) * 64, wn = (warp & 3) * 32;

    for (int bx = blockIdx.x; bx < 1616; bx += gridDim.x) {
        GemmJob jb;
        int M, rows_per_b, m0, n0;
        if (bx < 1536) {
            int z = bx >> 9;
            int r = bx & 511;
            jb = z == 0 ? j0 : z == 1 ? j1 : j2;
            m0 = (r >> 2) * 128; n0 = (r & 3) * 128;
            M = 16384; rows_per_b = 1024;
        } else {
            int c = bx - 1536;
            jb = (c < 40) ? j3 : j4;
            int r = c % 40;
            m0 = (r >> 2) * 128; n0 = (r & 3) * 128;
            M = 1232; rows_per_b = 77;
        }

        __syncthreads();
        float acc[4][4][4] = {};
        gemm_core(jb.A, jb.W, M, m0, n0, aBase, bBase, acc, tid, lane, wm, wn);

        #pragma unroll
        for (int i = 0; i < 4; i++) {
            #pragma unroll
            for (int rs = 0; rs < 2; rs++) {
                int gm = m0 + wm + i * 16 + g + rs * 8;
                if (gm >= M) continue;
                int bbi = gm / rows_per_b;
                int rr  = gm - bbi * rows_per_b;
                size_t orow = (size_t)bbi * jb.out_rows_per_b + jb.out_off + rr;
                #pragma unroll
                for (int j = 0; j < 4; j++) {
                    int col = n0 + wn + j * 8 + 2 * tg;
                    float v0 = acc[i][j][rs * 2 + 0] * jb.alpha;
                    float v1 = acc[i][j][rs * 2 + 1] * jb.alpha;
                    *(unsigned*)(jb.Out + orow * 512 + col) =
                        jb.outF16 ? pack_f16x2(v0, v1) : pack_bf16x2(v0, v1);
                }
            }
        }
    }
}

// Final projection GEMM (non-persistent, grid 512): fp32 out + residual.
__global__ void __launch_bounds__(256, 2)
gemm_final(const __nv_bfloat16* __restrict__ A, const __nv_bfloat16* __restrict__ W,
           float* __restrict__ Out, const float* __restrict__ Res)
{
    extern __shared__ char smc[];
    unsigned aBase = (unsigned)__cvta_generic_to_shared(smc);
    unsigned bBase = aBase + 3 * 16384;

    int tid = threadIdx.x, warp = tid >> 5, lane = tid & 31;
    int g = lane >> 2, tg = lane & 3;
    int wm = (warp >> 2) * 64, wn = (warp & 3) * 32;
    int m0 = blockIdx.x * 128, n0 = blockIdx.y * 128;

    float acc[4][4][4] = {};
    gemm_core(A, W, 16384, m0, n0, aBase, bBase, acc, tid, lane, wm, wn);

    #pragma unroll
    for (int i = 0; i < 4; i++) {
        #pragma unroll
        for (int rs = 0; rs < 2; rs++) {
            size_t orow = (size_t)(m0 + wm + i * 16 + g + rs * 8);
            #pragma unroll
            for (int j = 0; j < 4; j++) {
                int col = n0 + wn + j * 8 + 2 * tg;
                float2 rv = *(const float2*)(Res + orow * 512 + col);
                *(float2*)(Out + orow * 512 + col) =
                    make_float2(acc[i][j][rs * 2 + 0] + rv.x,
                                acc[i][j][rs * 2 + 1] + rv.y);
            }
        }
    }
}

// =====================================================================
// Persistent BF16/F16 flash attention, no-max softmax; exp2 interleaved
// per-chunk with P·V mma (short S->O dependency chains).
// =====================================================================
#define ATT_SMEM (65536 + 768)

__global__ void __launch_bounds__(256, 2)
attn_bf16(const int* __restrict__ tmask,
          const __nv_bfloat16* __restrict__ Qg,
          const __nv_bfloat16* __restrict__ Kg,
          const __nv_bfloat16* __restrict__ Vg,   // f16 bits
          __nv_bfloat16* __restrict__ Og)
{
    extern __shared__ char smc[];
    unsigned qB  = (unsigned)__cvta_generic_to_shared(smc);
    unsigned kvB = qB + 16384;
    float* kmaskf = (float*)(smc + 65536);

    int tid = threadIdx.x, warp = tid >> 5, lane = tid & 31;
    int g = lane >> 2, tg = lane & 3;
    int wm = warp * 16;

    for (int wk = blockIdx.x; wk < 1024; wk += gridDim.x) {
        int qt = wk & 7, h = (wk >> 3) & 7, b = wk >> 6;

        const __nv_bfloat16* qb = Qg + (size_t)(b * NN + qt * 128) * 512 + h * 64;
        const __nv_bfloat16* kb = Kg + (size_t)b * KVLEN * 512 + h * 64;
        const __nv_bfloat16* vb = Vg + (size_t)b * KVLEN * 512 + h * 64;
        const int* tm = tmask + b * LL;

        __syncthreads();

        #pragma unroll
        for (int i = 0; i < 4; i++) {
            int f = tid + i * 256;
            int r = f >> 3, c = f & 7;
            cpa16(qB + r * 128 + ((c ^ (r & 7)) << 4), qb + (size_t)r * 512 + c * 8, true);
        }

        auto loadKV = [&](int t, int stg) {
            int kv0 = t * 64;
            unsigned kD = kvB + stg * 16384, vD = kD + 8192;
            #pragma unroll
            for (int i = 0; i < 2; i++) {
                int f = tid + i * 256;
                int r = f >> 3, c = f & 7;
                int kg = kv0 + r;
                bool ok = kg < KVLEN;
                cpa16(kD + r * 128 + ((c ^ (r & 7)) << 4), kb + (size_t)kg * 512 + c * 8, ok);
                cpa16(vD + r * 128 + ((c ^ (r & 7)) << 4), vb + (size_t)kg * 512 + c * 8, ok);
            }
            if (kv0 + 64 > NN && tid < 64) {
                int kg = kv0 + tid;
                float m = 0.f;
                if (kg >= KVLEN) m = NEGV * LOG2E;
                else if (kg >= NN && tm[kg - NN] == 0) m = NEGV * LOG2E;
                kmaskf[stg * 64 + tid] = m;
            }
        };
        loadKV(0, 0); cpa_commit();
        loadKV(1, 1); cpa_commit();

        float l_i[2] = {0.f, 0.f}, o[8][4] = {};

        int st = 0;
        for (int t = 0; t < 18; t++) {
            if (t < 17) cpa_wait<1>(); else cpa_wait<0>();
            __syncthreads();
            if (t + 2 < 18) {
                int ns = st + 2; if (ns >= 3) ns -= 3;
                loadKV(t + 2, ns);
                cpa_commit();
            }

            unsigned kC = kvB + st * 16384;
            unsigned vC = kC + 8192;
            const float* km = kmaskf + st * 64;
            bool masked = (t * 64 + 64 > NN);

            // ---- S = Q K^T (bf16) ----
            float s[8][4] = {};
            #pragma unroll
            for (int kc = 0; kc < 8; kc += 2) {
                unsigned aq[4];
                {
                    int r = wm + (lane & 15);
                    int c = kc + (lane >> 4);
                    ldsm4(aq[0], aq[1], aq[2], aq[3], qB + r * 128 + ((c ^ (r & 7)) << 4));
                }
                #pragma unroll
                for (int grp = 0; grp < 4; grp++) {
                    int r = grp * 16 + (lane & 7) + ((lane >> 4) << 3);
                    int c = kc + ((lane >> 3) & 1);
                    unsigned r0, r1, r2, r3;
                    ldsm4(r0, r1, r2, r3, kC + r * 128 + ((c ^ (r & 7)) << 4));
                    unsigned bk0[2] = {r0, r1}, bk1[2] = {r2, r3};
                    mma16(s[grp * 2], aq, bk0);
                    mma16(s[grp * 2 + 1], aq, bk1);
                }
            }

            // ---- mask (final tiles only) ----
            if (masked) {
                #pragma unroll
                for (int j = 0; j < 8; j++) {
                    float k0v = km[j * 8 + 2 * tg], k1v = km[j * 8 + 2 * tg + 1];
                    s[j][0] += k0v; s[j][1] += k1v;
                    s[j][2] += k0v; s[j][3] += k1v;
                }
            }

            // ---- no-max softmax (f16x2 exp2) interleaved with P·V mma ----
            unsigned acc0 = 0u, acc1 = 0u;
            #pragma unroll
            for (int kc2 = 0; kc2 < 4; kc2++) {
                unsigned pp[4];
                pp[0] = hex2(pack_f16x2(s[2*kc2][0],   s[2*kc2][1]));
                pp[1] = hex2(pack_f16x2(s[2*kc2][2],   s[2*kc2][3]));
                pp[2] = hex2(pack_f16x2(s[2*kc2+1][0], s[2*kc2+1][1]));
                pp[3] = hex2(pack_f16x2(s[2*kc2+1][2], s[2*kc2+1][3]));
                acc0 = hadd2(acc0, hadd2(pp[0], pp[2]));
                acc1 = hadd2(acc1, hadd2(pp[1], pp[3]));
                #pragma unroll
                for (int grp = 0; grp < 4; grp++) {
                    int r = kc2 * 16 + (lane & 15);
                    int c = grp * 2 + (lane >> 4);
                    unsigned r0, r1, r2, r3;
                    ldsm4t(r0, r1, r2, r3, vC + r * 128 + ((c ^ (r & 7)) << 4));
                    unsigned bv0[2] = {r0, r1}, bv1[2] = {r2, r3};
                    mma16h(o[grp * 2], pp, bv0);
                    mma16h(o[grp * 2 + 1], pp, bv1);
                }
            }
            float2 s0 = unpack_h2(acc0);
            float2 s1 = unpack_h2(acc1);
            l_i[0] += s0.x + s0.y;
            l_i[1] += s1.x + s1.y;

            if (++st == 3) st = 0;
        }

        l_i[0] += __shfl_xor_sync(0xffffffffu, l_i[0], 1);
        l_i[0] += __shfl_xor_sync(0xffffffffu, l_i[0], 2);
        l_i[1] += __shfl_xor_sync(0xffffffffu, l_i[1], 1);
        l_i[1] += __shfl_xor_sync(0xffffffffu, l_i[1], 2);

        __nv_bfloat16* ob = Og + (size_t)(b * NN + qt * 128) * 512 + h * 64;
        #pragma unroll
        for (int rs = 0; rs < 2; rs++) {
            int r = wm + g + rs * 8;
            float inv = 1.f / l_i[rs];
            #pragma unroll
            for (int j = 0; j < 8; j++) {
                int col = j * 8 + 2 * tg;
                *(unsigned*)(ob + (size_t)r * 512 + col) =
                    pack_bf16x2(o[j][rs * 2 + 0] * inv, o[j][rs * 2 + 1] * inv);
            }
        }
    }
}

// =====================================================================
// launch
// =====================================================================
extern "C" void kernel_launch(void* const* d_in, const int* in_sizes, int n_in,
                              void* d_out, int out_size)
{
    const float* x    = (const float*)d_in[0];
    const float* te   = (const float*)d_in[1];
    const int*   tmk  = (const int*)  d_in[2];
    const float* gqs  = (const float*)d_in[3];
    const float* gqb  = (const float*)d_in[4];
    const float* gks  = (const float*)d_in[5];
    const float* gkb  = (const float*)d_in[6];
    const float* gts  = (const float*)d_in[7];
    const float* gtb  = (const float*)d_in[8];
    const float* Wq   = (const float*)d_in[9];
    const float* Wks  = (const float*)d_in[10];
    const float* Wvs  = (const float*)d_in[11];
    const float* Wkc  = (const float*)d_in[12];
    const float* Wvc  = (const float*)d_in[13];
    const float* Wout = (const float*)d_in[14];
    float* out = (float*)d_out;

    float* scratch = nullptr;
    cudaGetSymbolAddress((void**)&scratch, g_scratch);
    __nv_bfloat16* bs = (__nv_bfloat16*)scratch;
    __nv_bfloat16* XQ   = bs + BOFF_XQ;
    __nv_bfloat16* XKV  = bs + BOFF_XKV;
    __nv_bfloat16* Tb   = bs + BOFF_T;
    __nv_bfloat16* Qb   = bs + BOFF_Q;
    __nv_bfloat16* Kb   = bs + BOFF_K;
    __nv_bfloat16* Vb   = bs + BOFF_V;
    __nv_bfloat16* ATTb = bs + BOFF_ATT;
    __nv_bfloat16* Wb   = bs + BOFF_W;

    int nsm = 148;
    cudaDeviceGetAttribute(&nsm, cudaDevAttrMultiProcessorCount, 0);
    int pgrid = 2 * nsm;

    cudaFuncSetAttribute(gemm_all, cudaFuncAttributeMaxDynamicSharedMemorySize, GEMM_SMEM);
    cudaFuncSetAttribute(gemm_final, cudaFuncAttributeMaxDynamicSharedMemorySize, GEMM_SMEM);
    cudaFuncSetAttribute(attn_bf16, cudaFuncAttributeMaxDynamicSharedMemorySize, ATT_SMEM);

    prep_kernel<<<1408, 256>>>(x, gqs, gqb, gks, gkb,
                               te, gts, gtb,
                               Wq, Wks, Wvs, Wkc, Wvc, Wout,
                               XQ, XKV, Tb, Wb);

    __nv_bfloat16* WqB  = Wb;
    __nv_bfloat16* WksB = Wb + 262144;
    __nv_bfloat16* WvsB = Wb + 2 * 262144;
    __nv_bfloat16* WkcB = Wb + 3 * 262144;
    __nv_bfloat16* WvcB = Wb + 4 * 262144;
    __nv_bfloat16* WoB  = Wb + 5 * 262144;

    GemmJob jq  = { XQ,  WqB,  Qb, 0.125f * LOG2E, 1024,  0,    0 };
    GemmJob jk  = { XKV, WksB, Kb, 1.f,            KVLEN, 0,    0 };
    GemmJob jv  = { XKV, WvsB, Vb, 1.f,            KVLEN, 0,    1 };
    GemmJob jkc = { Tb,  WkcB, Kb, 1.f,            KVLEN, 1024, 0 };
    GemmJob jvc = { Tb,  WvcB, Vb, 1.f,            KVLEN, 1024, 1 };
    gemm_all<<<pgrid, 256, GEMM_SMEM>>>(jq, jk, jv, jkc, jvc);

    attn_bf16<<<pgrid, 256, ATT_SMEM>>>(tmk, Qb, Kb, Vb, ATTb);

    gemm_final<<<dim3(128, 4), 256, GEMM_SMEM>>>(ATTb, WoB, out, x);
}